// round 7
// baseline (speedup 1.0000x reference)
#include <cuda_runtime.h>
#include <math.h>
#include <stdint.h>

#define NTOK 16384
#define DIMC 512
#define NHEAD 8
#define DHD 64
#define FFI 1365
#define FFC1 683
#define CPBD 256
#define ATT_SCALE 0.125f

// ---------------- static scratch ----------------
__device__ float g_X1[NTOK * DIMC];
__device__ float g_X2[NTOK * DIMC];
__device__ float g_X3[NTOK * DIMC];
__device__ float g_XN[NTOK * DIMC];   // also generic GEMM output temp
__device__ float g_Qb[NTOK * DIMC];
__device__ float g_KVb[NTOK * DIMC * 2];
__device__ float g_AO[NTOK * DIMC];
__device__ float g_Hd[(size_t)NTOK * 2 * FFI];
__device__ float g_Yh[(size_t)NTOK * FFI];
__device__ float g_Yn[(size_t)NTOK * FFI];
__device__ float g_tabs[3969 * NHEAD];
__device__ float g_tabt[15 * NHEAD];
__device__ float g_biasS[(size_t)NHEAD * 1024 * 1024];

__device__ __forceinline__ float block_sum256(float v) {
    __shared__ float red[8];
    __shared__ float total;
#pragma unroll
    for (int m = 16; m; m >>= 1) v += __shfl_xor_sync(0xffffffffu, v, m);
    int t = threadIdx.x;
    if ((t & 31) == 0) red[t >> 5] = v;
    __syncthreads();
    if (t == 0) {
        float s = 0.f;
#pragma unroll
        for (int i = 0; i < 8; i++) s += red[i];
        total = s;
    }
    __syncthreads();
    return total;
}

// ---- input (b,c,f,h,w) -> X1[(b*8+f)*1024 + p][c] ----
__global__ void k_transpose_in(const float* __restrict__ x) {
    __shared__ float tile[32][33];
    int bf = blockIdx.z, b = bf >> 3, f = bf & 7;
    int p0 = blockIdx.x * 32, c0 = blockIdx.y * 32;
    int tx = threadIdx.x, ty = threadIdx.y;  // 32 x 8
#pragma unroll
    for (int i = 0; i < 4; i++) {
        int c = c0 + ty + i * 8;
        tile[ty + i * 8][tx] = x[(((size_t)(b * DIMC + c) * 8 + f) << 10) + p0 + tx];
    }
    __syncthreads();
#pragma unroll
    for (int i = 0; i < 4; i++) {
        int p = p0 + ty + i * 8;
        g_X1[((size_t)(bf << 10) + p) * DIMC + c0 + tx] = tile[tx][ty + i * 8];
    }
}

// ---- CPB MLP table ----
__global__ void k_cpb(const float* __restrict__ w1, const float* __restrict__ b1,
                      const float* __restrict__ w2, const float* __restrict__ b2,
                      const float* __restrict__ w3, const float* __restrict__ b3,
                      int spatial) {
    int r = blockIdx.x, t = threadIdx.x;  // 256
    __shared__ float h1[CPBD];
    __shared__ float h2[CPBD];
    float v;
    if (spatial) {
        float ry = (float)(r / 63) - 31.0f;
        float rx = (float)(r % 63) - 31.0f;
        v = ry * w1[t] + rx * w1[CPBD + t] + b1[t];
    } else {
        v = ((float)r - 7.0f) * w1[t] + b1[t];
    }
    h1[t] = v / (1.0f + __expf(-v));
    __syncthreads();
    float a = b2[t];
#pragma unroll 4
    for (int k = 0; k < CPBD; k++) a = fmaf(h1[k], w2[k * CPBD + t], a);
    h2[t] = a / (1.0f + __expf(-a));
    __syncthreads();
    if (t < NHEAD) {
        float o = b3[t];
#pragma unroll 4
        for (int k = 0; k < CPBD; k++) o = fmaf(h2[k], w3[k * NHEAD + t], o);
        (spatial ? g_tabs : g_tabt)[r * NHEAD + t] = o;
    }
}

// ---- materialize spatial bias: biasS[hd][i][j] ----
__global__ void k_bias_expand() {
    int i = blockIdx.x;
    int hd = blockIdx.y;
    int yi = i >> 5, xi = i & 31;
    size_t base = ((size_t)(hd << 10 | i)) << 10;
    for (int j = threadIdx.x; j < 1024; j += 256) {
        int dy = yi - (j >> 5), dx = xi - (j & 31);
        g_biasS[base + j] = g_tabs[((dy + 31) * 63 + (dx + 31)) * NHEAD + hd];
    }
}

// ---- RMSNorm over 512 ----
__global__ void k_rmsnorm(const float* __restrict__ X, const float* __restrict__ gamma,
                          float* __restrict__ Y) {
    int r = blockIdx.x, t = threadIdx.x;  // 256
    const float* xr = X + (size_t)r * DIMC;
    float a = xr[t], b = xr[t + 256];
    float tot = block_sum256(a * a + b * b);
    float sc = sqrtf(512.0f) / fmaxf(sqrtf(tot), 1e-12f);
    float* yr = Y + (size_t)r * DIMC;
    yr[t] = a * sc * gamma[t];
    yr[t + 256] = b * sc * gamma[t + 256];
}

// ---- SGEMM: C[16384 x N] = A[.,K] @ B[K,N]; 128x128x16 tile; VEC: float4 B loads ----
template <bool VEC>
__global__ void k_gemm(int N, int K,
                       const float* __restrict__ A, int lda,
                       const float* __restrict__ B, int ldb,
                       float* __restrict__ C) {
    __shared__ float As[16][129];
    __shared__ float Bs[16][128];
    const int t = threadIdx.x;  // 256
    const int ty = t >> 4, tx = t & 15;
    const int m0 = blockIdx.y * 128, n0 = blockIdx.x * 128;

    float acc[8][8];
#pragma unroll
    for (int i = 0; i < 8; i++)
#pragma unroll
        for (int j = 0; j < 8; j++) acc[i][j] = 0.f;

    for (int k0 = 0; k0 < K; k0 += 16) {
#pragma unroll
        for (int rep = 0; rep < 2; rep++) {
            int row = (t >> 2) + rep * 64;
            int kq = (t & 3) * 4;
            const float* ap = A + (size_t)(m0 + row) * lda + k0 + kq;
#pragma unroll
            for (int u = 0; u < 4; u++)
                As[kq + u][row] = (k0 + kq + u < K) ? ap[u] : 0.f;
        }
#pragma unroll
        for (int rep = 0; rep < 2; rep++) {
            int idx = t + rep * 256;
            int krow = idx >> 5, col = (idx & 31) * 4;
            if (VEC) {
                float4 v = make_float4(0.f, 0.f, 0.f, 0.f);
                if (k0 + krow < K && n0 + col < N)
                    v = *(const float4*)(B + (size_t)(k0 + krow) * ldb + n0 + col);
                *(float4*)&Bs[krow][col] = v;
            } else {
                const float* bp = B + (size_t)(k0 + krow) * ldb + n0 + col;
#pragma unroll
                for (int u = 0; u < 4; u++)
                    Bs[krow][col + u] =
                        (k0 + krow < K && n0 + col + u < N) ? bp[u] : 0.f;
            }
        }
        __syncthreads();
#pragma unroll
        for (int kk = 0; kk < 16; kk++) {
            float ar[8], br[8];
#pragma unroll
            for (int i = 0; i < 8; i++) ar[i] = As[kk][ty + i * 16];
#pragma unroll
            for (int j = 0; j < 8; j++) br[j] = Bs[kk][tx + j * 16];
#pragma unroll
            for (int i = 0; i < 8; i++)
#pragma unroll
                for (int j = 0; j < 8; j++) acc[i][j] = fmaf(ar[i], br[j], acc[i][j]);
        }
        __syncthreads();
    }
#pragma unroll
    for (int i = 0; i < 8; i++) {
        int r = m0 + ty + i * 16;
        float* cp = C + (size_t)r * N + n0 + tx;
#pragma unroll
        for (int j = 0; j < 8; j++)
            if (n0 + tx + j * 16 < N) cp[j * 16] = acc[i][j];
    }
}

// ---- residual adds + layout permutes ----
__global__ void k_add_s2t() {  // X2[tt] = G[r] + X1[r]   (r spatial)
    int r = blockIdx.x, t = threadIdx.x;
    int b = r >> 13, f = (r >> 10) & 7, p = r & 1023;
    int tt = (((b << 10) | p) << 3) | f;
    const float* gr = g_XN + (size_t)r * DIMC;
    const float* xr = g_X1 + (size_t)r * DIMC;
    float* o = g_X2 + (size_t)tt * DIMC;
    o[t] = gr[t] + xr[t];
    o[t + 256] = gr[t + 256] + xr[t + 256];
}
__global__ void k_add_t2s() {  // X3[ts] = G[r] + X2[r]   (r temporal)
    int r = blockIdx.x, t = threadIdx.x;
    int q = r >> 3, f = r & 7;
    int b = q >> 10, p = q & 1023;
    int ts = (b << 13) | (f << 10) | p;
    const float* gr = g_XN + (size_t)r * DIMC;
    const float* xr = g_X2 + (size_t)r * DIMC;
    float* o = g_X3 + (size_t)ts * DIMC;
    o[t] = gr[t] + xr[t];
    o[t + 256] = gr[t + 256] + xr[t + 256];
}
__global__ void k_add_final(float* __restrict__ out) {  // out[b,c,f,h,w]
    int r = blockIdx.x, t = threadIdx.x;
    int b = r >> 13, f = (r >> 10) & 7, p = r & 1023;
    const float* gr = g_XN + (size_t)r * DIMC;
    const float* xr = g_X3 + (size_t)r * DIMC;
    size_t base = ((size_t)b << 22) | ((size_t)f << 10) | (size_t)p;
#pragma unroll
    for (int u = 0; u < 2; u++) {
        int c = t + u * 256;
        out[base | ((size_t)c << 13)] = gr[c] + xr[c];
    }
}

// ---- GLU elementwise: Yh = a * gelu(gate) ----
__global__ void k_glu() {
    int r = blockIdx.y;
    int c = blockIdx.x * 256 + threadIdx.x;
    if (c >= FFI) return;
    const float* hr = g_Hd + (size_t)r * (2 * FFI);
    float a = hr[c], g = hr[c + FFI];
    float gel = 0.5f * g * (1.0f + erff(g * 0.70710678118654752f));
    g_Yh[(size_t)r * FFI + c] = a * gel;
}

// ---- FF temporal shift + RMSNorm over 1365 ----
__global__ void k_ffnorm(const float* __restrict__ gamma) {
    __shared__ float buf[FFI];
    int r = blockIdx.x, t = threadIdx.x;  // 256
    int f = (r >> 10) & 7;
    const float* yr = g_Yh + (size_t)r * FFI;
    float ss = 0.f;
    for (int c = t; c < FFI; c += 256) {
        float v;
        if (c < FFC1) v = yr[c];
        else v = (f > 0) ? g_Yh[(size_t)(r - 1024) * FFI + c] : 0.f;
        buf[c] = v;
        ss += v * v;
    }
    float tot = block_sum256(ss);
    float sc = sqrtf((float)FFI) / fmaxf(sqrtf(tot), 1e-12f);
    float* o = g_Yn + (size_t)r * FFI;
    for (int c = t; c < FFI; c += 256) o[c] = buf[c] * sc * gamma[c];
}

// ---- spatial flash attention: 64q x 32k tiles, materialized bias ----
__global__ void k_sattn() {
    __shared__ float Qk[64][65];
    __shared__ float Kk[64][33];
    __shared__ float Vs[32][65];
    __shared__ float Ps[64][33];
    const int t = threadIdx.x;  // 256
    const int ty = t >> 4, tx = t & 15;
    const int qb = blockIdx.x, hd = blockIdx.y, sq = blockIdx.z;

    {
        int r = t >> 2, d0 = (t & 3) * 16;
        const float* qp = g_Qb + (size_t)(sq * 1024 + qb * 64 + r) * DIMC + hd * DHD + d0;
#pragma unroll
        for (int u = 0; u < 16; u++) Qk[d0 + u][r] = qp[u];
    }
    float mi[4], li[4], o[4][4];
    size_t bbase[4];
#pragma unroll
    for (int ri = 0; ri < 4; ri++) {
        mi[ri] = -1e30f; li[ri] = 0.f;
#pragma unroll
        for (int cj = 0; cj < 4; cj++) o[ri][cj] = 0.f;
        int iq = qb * 64 + ty + ri * 16;
        bbase[ri] = ((size_t)(hd << 10 | iq)) << 10;
    }
    __syncthreads();

    for (int kt = 0; kt < 32; kt++) {
        int j0 = kt * 32;
        {
            int j = t >> 3, d0 = (t & 7) * 8;
            const float* kp = g_KVb + (size_t)(sq * 1024 + j0 + j) * 1024 + hd * DHD + d0;
#pragma unroll
            for (int u = 0; u < 8; u++) {
                Kk[d0 + u][j] = kp[u];
                Vs[j][d0 + u] = kp[512 + u];
            }
        }
        __syncthreads();

        float s[4][2];
#pragma unroll
        for (int ri = 0; ri < 4; ri++) { s[ri][0] = 0.f; s[ri][1] = 0.f; }
#pragma unroll 8
        for (int kk = 0; kk < 64; kk++) {
            float k0v = Kk[kk][tx], k1v = Kk[kk][tx + 16];
#pragma unroll
            for (int ri = 0; ri < 4; ri++) {
                float qv = Qk[kk][ty + ri * 16];
                s[ri][0] = fmaf(qv, k0v, s[ri][0]);
                s[ri][1] = fmaf(qv, k1v, s[ri][1]);
            }
        }
#pragma unroll
        for (int ri = 0; ri < 4; ri++) {
            s[ri][0] = s[ri][0] * ATT_SCALE + g_biasS[bbase[ri] + j0 + tx];
            s[ri][1] = s[ri][1] * ATT_SCALE + g_biasS[bbase[ri] + j0 + tx + 16];
            float mx = fmaxf(s[ri][0], s[ri][1]);
#pragma unroll
            for (int m = 1; m < 16; m <<= 1) mx = fmaxf(mx, __shfl_xor_sync(0xffffffffu, mx, m));
            float mn = fmaxf(mi[ri], mx);
            float al = __expf(mi[ri] - mn);
            float p0 = __expf(s[ri][0] - mn);
            float p1 = __expf(s[ri][1] - mn);
            float rs = p0 + p1;
#pragma unroll
            for (int m = 1; m < 16; m <<= 1) rs += __shfl_xor_sync(0xffffffffu, rs, m);
            li[ri] = li[ri] * al + rs;
            mi[ri] = mn;
#pragma unroll
            for (int cj = 0; cj < 4; cj++) o[ri][cj] *= al;
            Ps[ty + ri * 16][tx] = p0;
            Ps[ty + ri * 16][tx + 16] = p1;
        }
        __syncthreads();
#pragma unroll 4
        for (int kk = 0; kk < 32; kk++) {
            float vr[4], pv[4];
#pragma unroll
            for (int cj = 0; cj < 4; cj++) vr[cj] = Vs[kk][tx + cj * 16];
#pragma unroll
            for (int ri = 0; ri < 4; ri++) pv[ri] = Ps[ty + ri * 16][kk];
#pragma unroll
            for (int ri = 0; ri < 4; ri++)
#pragma unroll
                for (int cj = 0; cj < 4; cj++) o[ri][cj] = fmaf(pv[ri], vr[cj], o[ri][cj]);
        }
        __syncthreads();
    }
#pragma unroll
    for (int ri = 0; ri < 4; ri++) {
        float inv = 1.0f / li[ri];
        float* op = g_AO + (size_t)(sq * 1024 + qb * 64 + ty + ri * 16) * DIMC + hd * DHD + tx;
#pragma unroll
        for (int cj = 0; cj < 4; cj++) op[cj * 16] = o[ri][cj] * inv;
    }
}

// ---- temporal attention: seq len 8 ----
__global__ void k_tattn() {
    __shared__ float q[8][65], k[8][65], v[8][65], p[8][9];
    int t = threadIdx.x;  // 64
    int sq = blockIdx.x, hd = blockIdx.y;
#pragma unroll
    for (int i = 0; i < 8; i++) {
        size_t tok = (size_t)sq * 8 + i;
        q[i][t] = g_Qb[tok * DIMC + hd * DHD + t];
        k[i][t] = g_KVb[tok * 1024 + hd * DHD + t];
        v[i][t] = g_KVb[tok * 1024 + 512 + hd * DHD + t];
    }
    __syncthreads();
    {
        int i = t >> 3, j = t & 7;
        float s = 0.f;
#pragma unroll
        for (int d = 0; d < 64; d++) s = fmaf(q[i][d], k[j][d], s);
        p[i][j] = s * ATT_SCALE + g_tabt[(i - j + 7) * NHEAD + hd];
    }
    __syncthreads();
    if (t < 8) {
        float mx = -1e30f;
#pragma unroll
        for (int j = 0; j < 8; j++) mx = fmaxf(mx, p[t][j]);
        float sm = 0.f, e[8];
#pragma unroll
        for (int j = 0; j < 8; j++) { e[j] = __expf(p[t][j] - mx); sm += e[j]; }
        float inv = 1.0f / sm;
#pragma unroll
        for (int j = 0; j < 8; j++) p[t][j] = e[j] * inv;
    }
    __syncthreads();
#pragma unroll
    for (int i = 0; i < 8; i++) {
        float o = 0.f;
#pragma unroll
        for (int j = 0; j < 8; j++) o = fmaf(p[i][j], v[j][t], o);
        g_AO[((size_t)sq * 8 + i) * DIMC + hd * DHD + t] = o;
    }
}

extern "C" void kernel_launch(void* const* d_in, const int* in_sizes, int n_in,
                              void* d_out, int out_size) {
    const float* x = (const float*)d_in[0];
    const float* sa_gamma = (const float*)d_in[1];
    const float* sa_wq = (const float*)d_in[2];
    const float* sa_wkv = (const float*)d_in[3];
    const float* sa_wo = (const float*)d_in[4];
    const float* ta_gamma = (const float*)d_in[5];
    const float* ta_wq = (const float*)d_in[6];
    const float* ta_wkv = (const float*)d_in[7];
    const float* ta_wo = (const float*)d_in[8];
    const float* sp_w1 = (const float*)d_in[9];
    const float* sp_b1 = (const float*)d_in[10];
    const float* sp_w2 = (const float*)d_in[11];
    const float* sp_b2 = (const float*)d_in[12];
    const float* sp_w3 = (const float*)d_in[13];
    const float* sp_b3 = (const float*)d_in[14];
    const float* tp_w1 = (const float*)d_in[15];
    const float* tp_b1 = (const float*)d_in[16];
    const float* tp_w2 = (const float*)d_in[17];
    const float* tp_b2 = (const float*)d_in[18];
    const float* tp_w3 = (const float*)d_in[19];
    const float* tp_b3 = (const float*)d_in[20];
    const float* ff_win = (const float*)d_in[21];
    const float* ff_gamma = (const float*)d_in[22];
    const float* ff_wout = (const float*)d_in[23];
    float* out = (float*)d_out;

    float *X1, *X2, *X3, *XN, *Qb, *KVb, *AO, *Hd, *Yn;
    cudaGetSymbolAddress((void**)&X1, g_X1);
    cudaGetSymbolAddress((void**)&X2, g_X2);
    cudaGetSymbolAddress((void**)&X3, g_X3);
    cudaGetSymbolAddress((void**)&XN, g_XN);
    cudaGetSymbolAddress((void**)&Qb, g_Qb);
    cudaGetSymbolAddress((void**)&KVb, g_KVb);
    cudaGetSymbolAddress((void**)&AO, g_AO);
    cudaGetSymbolAddress((void**)&Hd, g_Hd);
    cudaGetSymbolAddress((void**)&Yn, g_Yn);

    k_transpose_in<<<dim3(32, 16, 16), dim3(32, 8)>>>(x);
    k_cpb<<<3969, 256>>>(sp_w1, sp_b1, sp_w2, sp_b2, sp_w3, sp_b3, 1);
    k_cpb<<<15, 256>>>(tp_w1, tp_b1, tp_w2, tp_b2, tp_w3, tp_b3, 0);
    k_bias_expand<<<dim3(1024, 8), 256>>>();

    // ---- spatial attention block ----
    k_rmsnorm<<<NTOK, 256>>>(X1, sa_gamma, XN);
    k_gemm<true><<<dim3(4, 128), 256>>>(512, 512, XN, 512, sa_wq, 512, Qb);
    k_gemm<true><<<dim3(8, 128), 256>>>(1024, 512, XN, 512, sa_wkv, 1024, KVb);
    k_sattn<<<dim3(16, 8, 16), 256>>>();
    k_gemm<true><<<dim3(4, 128), 256>>>(512, 512, AO, 512, sa_wo, 512, XN);
    k_add_s2t<<<NTOK, 256>>>();

    // ---- temporal attention block ----
    k_rmsnorm<<<NTOK, 256>>>(X2, ta_gamma, XN);
    k_gemm<true><<<dim3(4, 128), 256>>>(512, 512, XN, 512, ta_wq, 512, Qb);
    k_gemm<true><<<dim3(8, 128), 256>>>(1024, 512, XN, 512, ta_wkv, 1024, KVb);
    k_tattn<<<dim3(2048, 8), 64>>>();
    k_gemm<true><<<dim3(4, 128), 256>>>(512, 512, AO, 512, ta_wo, 512, XN);
    k_add_t2s<<<NTOK, 256>>>();

    // ---- FF block ----
    k_gemm<false><<<dim3(22, 128), 256>>>(2 * FFI, 512, X3, 512, ff_win, 2 * FFI, Hd);
    k_glu<<<dim3(6, NTOK), 256>>>();
    k_ffnorm<<<NTOK, 256>>>(ff_gamma);
    k_gemm<true><<<dim3(4, 128), 256>>>(512, FFI, Yn, FFI, ff_wout, 512, XN);
    k_add_final<<<NTOK, 256>>>(out);
}